// round 8
// baseline (speedup 1.0000x reference)
#include <cuda_runtime.h>

#define D_TOT 65536
#define S_TOT 1024
#define NBLK  (D_TOT / 32)   // 2048 blocks
#define EPS   0.02f          // |bundled| below this -> precise-trig recompute

__device__ float        g_part[NBLK];
__device__ unsigned int g_ctr;   // zero at load; reset by the reducing block each call

// Warp-decoupled structure: block = 32 d-rows; warp w owns s-stripe
// [w*128, w*128+128) with a PRIVATE 32x33 smem tile. Transpose needs only
// __syncwarp(), so the 8 warps drift freely -> no block-wide load/store
// phase lockstep, DRAM requests stay continuously in flight.
__global__ __launch_bounds__(256, 5) void reghd_main(
    const float* __restrict__ x,
    const float* __restrict__ weight,
    const float* __restrict__ bias,
    const float* __restrict__ alpha,
    const float* __restrict__ M,
    float* __restrict__ out)   // [0]=model_result, [1..D]=q, [1+D ...]=hvs (SIZE,D)
{
    __shared__ float sx[S_TOT];
    __shared__ float sa[S_TOT];
    __shared__ float tile[8][32][33];   // per-warp private transpose tiles
    __shared__ float bpart[8][32];      // per-warp bundled partials
    __shared__ float red[256];
    __shared__ bool  is_last;

    const int tx  = threadIdx.x;        // 0..31
    const int w   = threadIdx.y;        // warp id 0..7
    const int tid = w * 32 + tx;
    const int d0  = blockIdx.x * 32;

    ((float4*)sx)[tid] = ((const float4*)x)[tid];
    ((float4*)sa)[tid] = ((const float4*)alpha)[tid];
    __syncthreads();

    float acc = 0.f;                    // bundled partial: row d0+tx over warp's s-stripe
    float* __restrict__ hvs = out + 1 + D_TOT;

    const int g = tx >> 3;              // 0..3
    const int m = tx & 7;               // 0..7

    for (int t = 0; t < 4; t++) {       // 4 subtiles of 32 s within this warp's stripe
        const int so = w * 128 + t * 32;

        // ---- load + trig + warp-local transpose write ----
        #pragma unroll
        for (int r = 0; r < 8; r++) {
            const int    dl   = r * 4 + g;              // d-row within block
            const int    sc   = 4 * m;                  // s within subtile
            const size_t base = (size_t)(d0 + dl) * S_TOT + (size_t)(so + sc);
            const float4 w4 = __ldcs((const float4*)(weight + base));
            const float4 b4 = __ldcs((const float4*)(bias   + base));
            const float  x0 = sx[so + sc + 0], x1 = sx[so + sc + 1];
            const float  x2 = sx[so + sc + 2], x3 = sx[so + sc + 3];

            const float p0 = x0 * w4.x, p1 = x1 * w4.y;
            const float p2 = x2 * w4.z, p3 = x3 * w4.w;
            // STS banks: (dl*33 + sc + i) mod 32 = (g + 4m + i) mod 32 -> permutation
            tile[w][dl][sc + 0] = __cosf(p0 + b4.x) * __sinf(p0);
            tile[w][dl][sc + 1] = __cosf(p1 + b4.y) * __sinf(p1);
            tile[w][dl][sc + 2] = __cosf(p2 + b4.z) * __sinf(p2);
            tile[w][dl][sc + 3] = __cosf(p3 + b4.w) * __sinf(p3);
        }
        __syncwarp();

        // ---- transposed store + bundled accumulate (lane tx owns d-row tx) ----
        #pragma unroll
        for (int sl = 0; sl < 32; sl++) {
            const float e = tile[w][tx][sl];            // stride 33 -> conflict-free
            acc = fmaf(e, sa[so + sl], acc);
            __stcs(&hvs[(size_t)(so + sl) * D_TOT + (size_t)(d0 + tx)], e);
        }
        __syncwarp();
    }

    bpart[w][tx] = acc;
    __syncthreads();

    // Warp 0: combine warp partials, guarded sign, q, dot(q,M) partial.
    if (w == 0) {
        float v = 0.f;
        #pragma unroll
        for (int j = 0; j < 8; j++) v += bpart[j][tx];   // row d0+tx total

        // Ballot-driven precise fallback: loop is warp-uniform, full-mask
        // collectives inside are legal. ~0.16% of rows flagged.
        unsigned flag = __ballot_sync(0xFFFFFFFFu, fabsf(v) < EPS);
        while (flag) {
            const int r = __ffs(flag) - 1;
            flag &= flag - 1;
            const int d = d0 + r;
            float s2 = 0.f;
            for (int s = tx; s < S_TOT; s += 32) {
                const float wv = weight[(size_t)d * S_TOT + s];
                const float bv = bias[(size_t)d * S_TOT + s];
                const float pp = sx[s] * wv;
                s2 += cosf(pp + bv) * sinf(pp) * sa[s];
            }
            #pragma unroll
            for (int off = 16; off > 0; off >>= 1)
                s2 += __shfl_xor_sync(0xFFFFFFFFu, s2, off);
            if (tx == r) v = s2;
        }

        const float q = (v > 0.f) ? 1.f : -1.f;
        out[1 + d0 + tx] = q;
        float qm = q * M[d0 + tx];
        #pragma unroll
        for (int off = 16; off > 0; off >>= 1)
            qm += __shfl_xor_sync(0xFFFFFFFFu, qm, off);
        if (tx == 0) {
            g_part[blockIdx.x] = qm;
            __threadfence();
            const unsigned int prev = atomicAdd(&g_ctr, 1u);
            is_last = (prev == NBLK - 1);
        }
    }
    __syncthreads();

    // Last-arriving block reduces all partials (fixed order -> deterministic).
    if (is_last) {
        float s = 0.f;
        for (int i = tid; i < NBLK; i += 256)
            s += g_part[i];
        red[tid] = s;
        __syncthreads();
        #pragma unroll
        for (int k = 128; k > 0; k >>= 1) {
            if (tid < k) red[tid] += red[tid + k];
            __syncthreads();
        }
        if (tid == 0) {
            out[0] = red[0];
            g_ctr  = 0;          // reset for next graph replay
        }
    }
}

extern "C" void kernel_launch(void* const* d_in, const int* in_sizes, int n_in,
                              void* d_out, int out_size) {
    const float* x      = (const float*)d_in[0];
    const float* weight = (const float*)d_in[1];
    const float* bias   = (const float*)d_in[2];
    const float* alpha  = (const float*)d_in[3];
    const float* M      = (const float*)d_in[4];
    float* out = (float*)d_out;

    dim3 blk(32, 8);
    reghd_main<<<NBLK, blk>>>(x, weight, bias, alpha, M, out);
}

// round 9
// speedup vs baseline: 1.2421x; 1.2421x over previous
#include <cuda_runtime.h>

#define D_TOT 65536
#define S_TOT 1024
#define TS    64
#define NBLK  (D_TOT / 32)   // 2048 blocks
#define EPS   0.02f          // |bundled| below this -> precise-trig recompute

__device__ float        g_part[NBLK];
__device__ unsigned int g_ctr;   // zero at load; reset by the reducing block each call

// R3 footprint (26KB smem, occ 6, ~40 regs) with a ping-pong 32x64 tile and
// ONE barrier per tile: store(t) and compute(t+1) overlap with no barrier
// between them, so each warp's next-tile LDGs issue during its STG burst.
// Buffer reuse is safe: compute(t+2) writing buf[p] sits after barrier(t+1),
// which all warps reach only after finishing store(t) from buf[p].
__global__ __launch_bounds__(256, 6) void reghd_main(
    const float* __restrict__ x,
    const float* __restrict__ weight,
    const float* __restrict__ bias,
    const float* __restrict__ alpha,
    const float* __restrict__ M,
    float* __restrict__ out)   // [0]=model_result, [1..D]=q, [1+D ...]=hvs (SIZE,D)
{
    __shared__ float4 sx[S_TOT / 4];
    __shared__ float4 sa[S_TOT / 4];
    __shared__ float  tile[2][32][TS + 1];  // 2 x 8.3KB, pad 65: LDS side conflict-free
    __shared__ float  bpart[32];
    __shared__ float  red[256];
    __shared__ bool   is_last;

    const int tx  = threadIdx.x;             // 0..31
    const int ty  = threadIdx.y;             // 0..7 (warp id)
    const int tid = ty * 32 + tx;
    const int d0  = blockIdx.x * 32;
    const int h   = tx >> 4;                 // row-half within warp (0/1)
    const int m   = tx & 15;                 // s-lane within half
    const int sc  = 4 * m;                   // s within tile (0..60)

    sx[tid] = ((const float4*)x)[tid];
    sa[tid] = ((const float4*)alpha)[tid];
    __syncthreads();

    // Warp ty owns d-rows ty + 8*(h + 2r), r=0..1 -> {ty, ty+8, ty+16, ty+24}.
    float acc[2] = {0.f, 0.f};
    float* __restrict__ hvs = out + 1 + D_TOT;

    int p = 0;
    for (int s0 = 0; s0 < S_TOT; s0 += TS) {
        const float4 xv = sx[(s0 + sc) >> 2];
        const float4 av = sa[(s0 + sc) >> 2];

        #pragma unroll
        for (int r = 0; r < 2; r++) {
            const int    dl   = ty + 8 * (h + 2 * r);
            const size_t base = (size_t)(d0 + dl) * S_TOT + (size_t)(s0 + sc);
            const float4 w = __ldcs((const float4*)(weight + base));
            const float4 b = __ldcs((const float4*)(bias   + base));

            const float p0 = xv.x * w.x, p1 = xv.y * w.y;
            const float p2 = xv.z * w.z, p3 = xv.w * w.w;
            const float e0 = __cosf(p0 + b.x) * __sinf(p0);
            const float e1 = __cosf(p1 + b.y) * __sinf(p1);
            const float e2 = __cosf(p2 + b.z) * __sinf(p2);
            const float e3 = __cosf(p3 + b.w) * __sinf(p3);

            tile[p][dl][sc + 0] = e0;
            tile[p][dl][sc + 1] = e1;
            tile[p][dl][sc + 2] = e2;
            tile[p][dl][sc + 3] = e3;

            acc[r] += fmaf(e0, av.x, fmaf(e1, av.y, fmaf(e2, av.z, e3 * av.w)));
        }

        __syncthreads();   // buf[p] complete; also fences buf[p^1] reuse (see header)

        #pragma unroll
        for (int k = 0; k < 8; k++) {
            const int sl = ty + 8 * k;      // 8 warps x 8 -> 64 s-rows
            __stcs(&hvs[(size_t)(s0 + sl) * D_TOT + (size_t)(d0 + tx)], tile[p][tx][sl]);
        }
        p ^= 1;            // no barrier: next compute targets the other buffer
    }

    // Reduce acc over the 16 lanes of each half (xor<16 keeps halves separate).
    #pragma unroll
    for (int r = 0; r < 2; r++) {
        float v = acc[r];
        v += __shfl_xor_sync(0xFFFFFFFFu, v, 1);
        v += __shfl_xor_sync(0xFFFFFFFFu, v, 2);
        v += __shfl_xor_sync(0xFFFFFFFFu, v, 4);
        v += __shfl_xor_sync(0xFFFFFFFFu, v, 8);
        if (m == 0) bpart[ty + 8 * (h + 2 * r)] = v;   // full row total
    }
    __syncthreads();

    // Warp 0: guarded sign, q, dot(q,M) partial.
    if (ty == 0) {
        float v = bpart[tx];

        // Ballot-driven precise fallback: warp-uniform loop, full-mask legal.
        unsigned flag = __ballot_sync(0xFFFFFFFFu, fabsf(v) < EPS);
        const float* xs = (const float*)sx;
        const float* as = (const float*)sa;
        while (flag) {
            const int r = __ffs(flag) - 1;
            flag &= flag - 1;
            const int d = d0 + r;
            float s2 = 0.f;
            for (int s = tx; s < S_TOT; s += 32) {
                const float wv = weight[(size_t)d * S_TOT + s];
                const float bv = bias[(size_t)d * S_TOT + s];
                const float pp = xs[s] * wv;
                s2 += cosf(pp + bv) * sinf(pp) * as[s];
            }
            #pragma unroll
            for (int off = 16; off > 0; off >>= 1)
                s2 += __shfl_xor_sync(0xFFFFFFFFu, s2, off);
            if (tx == r) v = s2;
        }

        const float q = (v > 0.f) ? 1.f : -1.f;
        out[1 + d0 + tx] = q;
        float qm = q * M[d0 + tx];
        #pragma unroll
        for (int off = 16; off > 0; off >>= 1)
            qm += __shfl_xor_sync(0xFFFFFFFFu, qm, off);
        if (tx == 0) {
            g_part[blockIdx.x] = qm;
            __threadfence();
            const unsigned int prev = atomicAdd(&g_ctr, 1u);
            is_last = (prev == NBLK - 1);
        }
    }
    __syncthreads();

    // Last-arriving block reduces all partials (fixed order -> deterministic).
    if (is_last) {
        float s = 0.f;
        for (int i = tid; i < NBLK; i += 256)
            s += g_part[i];
        red[tid] = s;
        __syncthreads();
        #pragma unroll
        for (int k = 128; k > 0; k >>= 1) {
            if (tid < k) red[tid] += red[tid + k];
            __syncthreads();
        }
        if (tid == 0) {
            out[0] = red[0];
            g_ctr  = 0;          // reset for next graph replay
        }
    }
}

extern "C" void kernel_launch(void* const* d_in, const int* in_sizes, int n_in,
                              void* d_out, int out_size) {
    const float* x      = (const float*)d_in[0];
    const float* weight = (const float*)d_in[1];
    const float* bias   = (const float*)d_in[2];
    const float* alpha  = (const float*)d_in[3];
    const float* M      = (const float*)d_in[4];
    float* out = (float*)d_out;

    dim3 blk(32, 8);
    reghd_main<<<NBLK, blk>>>(x, weight, bias, alpha, M, out);
}